// round 11
// baseline (speedup 1.0000x reference)
#include <cuda_runtime.h>
#include <cstdint>

// Problem constants (fixed shapes per reference)
#define NN 50000
#define EE 800000
#define IN_F 128
#define KTOP 32

// Scratch (static device globals: allocation-free)
__device__ int   g_deg[NN];
__device__ int   g_rowptr[NN + 1];
__device__ int   g_cursor[NN];
__device__ int   g_csrc[EE];
__device__ float g_y[(size_t)NN * IN_F];       // y = x_sparse @ W_neigh

// ---------------------------------------------------------------------------
// Kernel 1: zero deg
// ---------------------------------------------------------------------------
__global__ void k_zero_deg() {
    int i = blockIdx.x * blockDim.x + threadIdx.x;
    if (i < NN) g_deg[i] = 0;
}

// ---------------------------------------------------------------------------
// Kernel 2: in-degree histogram over dst (4 edges/thread, vectorized load)
// ---------------------------------------------------------------------------
__global__ void k_deg(const int* __restrict__ dst) {
    int i = blockIdx.x * blockDim.x + threadIdx.x;   // int4 index
    if (i * 4 + 3 < EE) {
        int4 d = reinterpret_cast<const int4*>(dst)[i];
        atomicAdd(&g_deg[d.x], 1);
        atomicAdd(&g_deg[d.y], 1);
        atomicAdd(&g_deg[d.z], 1);
        atomicAdd(&g_deg[d.w], 1);
    } else {
        for (int j = i * 4; j < EE; j++) atomicAdd(&g_deg[dst[j]], 1);
    }
}

// ---------------------------------------------------------------------------
// Kernel 3: single-block exclusive prefix scan of deg -> rowptr (+cursor copy)
// ---------------------------------------------------------------------------
#define SCAN_T 1024
#define SCAN_CH 49

__global__ __launch_bounds__(SCAN_T)
void k_scan() {
    __shared__ int sums[SCAN_T];
    int t = threadIdx.x;
    int base = t * SCAN_CH;

    int s = 0;
    #pragma unroll 7
    for (int i = 0; i < SCAN_CH; i++) {
        int j = base + i;
        if (j < NN) s += g_deg[j];
    }
    sums[t] = s;
    __syncthreads();

    for (int off = 1; off < SCAN_T; off <<= 1) {
        int tmp = 0;
        if (t >= off) tmp = sums[t - off];
        __syncthreads();
        if (t >= off) sums[t] += tmp;
        __syncthreads();
    }
    int run = sums[t] - s;

    #pragma unroll 7
    for (int i = 0; i < SCAN_CH; i++) {
        int j = base + i;
        if (j < NN) {
            g_rowptr[j] = run;
            g_cursor[j] = run;
            run += g_deg[j];
        }
    }
    if (t == 0) g_rowptr[NN] = EE;
}

// ---------------------------------------------------------------------------
// Kernel 4: fill CSR src lists (order within node arbitrary). 2 edges/thread.
// ---------------------------------------------------------------------------
__global__ void k_fill(const int* __restrict__ src, const int* __restrict__ dst) {
    int i = blockIdx.x * blockDim.x + threadIdx.x;   // int2 index
    if (i * 2 + 1 < EE) {
        int2 d = reinterpret_cast<const int2*>(dst)[i];
        int2 s = reinterpret_cast<const int2*>(src)[i];
        int p0 = atomicAdd(&g_cursor[d.x], 1);
        int p1 = atomicAdd(&g_cursor[d.y], 1);
        g_csrc[p0] = s.x;
        g_csrc[p1] = s.y;
    } else {
        for (int j = i * 2; j < EE; j++) {
            int pos = atomicAdd(&g_cursor[dst[j]], 1);
            g_csrc[pos] = src[j];
        }
    }
}

// ---------------------------------------------------------------------------
// Kernel 5: y[s] = x_sparse[s] @ W_neigh — one warp per node, all 128 cols in
// one pass. Dedup'd (v,ix) staged in smem; W_neigh (64KB) served from L1.
// ---------------------------------------------------------------------------
#define SG_WARPS 8

__global__ __launch_bounds__(256)
void k_sparse_gemm(const float* __restrict__ topk_values,
                   const int*   __restrict__ topk_indices,
                   const float* __restrict__ Wneigh) {
    __shared__ float s_v[SG_WARPS][KTOP];
    __shared__ int   s_ix[SG_WARPS][KTOP];
    const int w    = threadIdx.x >> 5;
    const int lane = threadIdx.x & 31;
    const int node = blockIdx.x * SG_WARPS + w;
    if (node >= NN) return;

    float v  = topk_values[(size_t)node * KTOP + lane];
    int   ix = topk_indices[(size_t)node * KTOP + lane];
    unsigned peers = __match_any_sync(0xffffffffu, ix);
    if (lane != (31 - __clz(peers))) v = 0.f;      // last-wins dedup
    s_v[w][lane]  = v;
    s_ix[w][lane] = ix;
    __syncwarp();

    float4 acc = make_float4(0.f, 0.f, 0.f, 0.f);
    #pragma unroll 8
    for (int k = 0; k < KTOP; k++) {
        float vk = s_v[w][k];                      // broadcast LDS
        int   ik = s_ix[w][k];                     // broadcast LDS
        float4 wv = __ldg(reinterpret_cast<const float4*>(
                        Wneigh + (size_t)ik * IN_F + lane * 4));
        acc.x = fmaf(vk, wv.x, acc.x);
        acc.y = fmaf(vk, wv.y, acc.y);
        acc.z = fmaf(vk, wv.z, acc.z);
        acc.w = fmaf(vk, wv.w, acc.w);
    }
    *reinterpret_cast<float4*>(g_y + (size_t)node * IN_F + lane * 4) = acc;
}

// ---------------------------------------------------------------------------
// Kernel 6: out[d] += (1/max(deg,1)) * sum_{e: dst=d} y[src_e]
// ---------------------------------------------------------------------------
__global__ __launch_bounds__(256)
void k_gather_add(float* __restrict__ out) {
    const int w    = threadIdx.x >> 5;
    const int lane = threadIdx.x & 31;
    const int node = blockIdx.x * 8 + w;
    if (node >= NN) return;

    const int beg = g_rowptr[node];
    const int end = g_rowptr[node + 1];
    const float4* y4 = reinterpret_cast<const float4*>(g_y);

    float4 a0 = make_float4(0.f, 0.f, 0.f, 0.f);
    float4 a1 = make_float4(0.f, 0.f, 0.f, 0.f);
    float4 a2 = make_float4(0.f, 0.f, 0.f, 0.f);
    float4 a3 = make_float4(0.f, 0.f, 0.f, 0.f);

    int e = beg;
    for (; e + 3 < end; e += 4) {
        int s0 = g_csrc[e + 0];
        int s1 = g_csrc[e + 1];
        int s2 = g_csrc[e + 2];
        int s3 = g_csrc[e + 3];
        float4 v0 = y4[(size_t)s0 * 32 + lane];
        float4 v1 = y4[(size_t)s1 * 32 + lane];
        float4 v2 = y4[(size_t)s2 * 32 + lane];
        float4 v3 = y4[(size_t)s3 * 32 + lane];
        a0.x += v0.x; a0.y += v0.y; a0.z += v0.z; a0.w += v0.w;
        a1.x += v1.x; a1.y += v1.y; a1.z += v1.z; a1.w += v1.w;
        a2.x += v2.x; a2.y += v2.y; a2.z += v2.z; a2.w += v2.w;
        a3.x += v3.x; a3.y += v3.y; a3.z += v3.z; a3.w += v3.w;
    }
    for (; e < end; e++) {
        int s0 = g_csrc[e];
        float4 v0 = y4[(size_t)s0 * 32 + lane];
        a0.x += v0.x; a0.y += v0.y; a0.z += v0.z; a0.w += v0.w;
    }

    float winv = 1.0f / fmaxf((float)(end - beg), 1.0f);
    float* op = out + (size_t)node * IN_F + lane * 4;
    float4 cur = *reinterpret_cast<const float4*>(op);
    float4 r;
    r.x = cur.x + (a0.x + a1.x + a2.x + a3.x) * winv;
    r.y = cur.y + (a0.y + a1.y + a2.y + a3.y) * winv;
    r.z = cur.z + (a0.z + a1.z + a2.z + a3.z) * winv;
    r.w = cur.w + (a0.w + a1.w + a2.w + a3.w) * winv;
    *reinterpret_cast<float4*>(op) = r;
}

// ---------------------------------------------------------------------------
// Kernel 7: out = feat @ W_self + b_self   (M=NN, N=128, K=128)
// 3xTF32 tensor-core GEMM with FRAGMENT-PACKED smem staging:
// hi/lo tiles are stored in mma-fragment order so the mainloop fetches each
// fragment with one LDS.128 (12 vector loads + 48 mma per k8-step, vs 96
// scalar LDS before).
//   A frag layout: slotA=((wm*2+mi)*2+ks8), word = slotA*128 + lane*4 + reg,
//     reg = kh*2 + mhalf   (a0..a3 of m16n8k8)
//   B frag layout: slotB=((wn*4+nip)*2+ks8), word = slotB*128 + lane*4 + reg,
//     reg = (ni&1)*2 + kh  (two adjacent-ni fragments per 16B)
// ---------------------------------------------------------------------------
#define BM 128
#define BN 128
#define BK 16

__device__ __forceinline__ void split_tf32(float x, uint32_t& hi, uint32_t& lo) {
    uint32_t h;
    asm("cvt.rna.tf32.f32 %0, %1;" : "=r"(h) : "f"(x));
    float lf = x - __uint_as_float(h);
    uint32_t l;
    asm("cvt.rna.tf32.f32 %0, %1;" : "=r"(l) : "f"(lf));
    hi = h; lo = l;
}

__device__ __forceinline__ void mma_tf32(float* d, const uint32_t* a,
                                         uint32_t b0, uint32_t b1) {
    asm volatile(
        "mma.sync.aligned.m16n8k8.row.col.f32.tf32.tf32.f32 "
        "{%0,%1,%2,%3}, {%4,%5,%6,%7}, {%8,%9}, {%0,%1,%2,%3};"
        : "+f"(d[0]), "+f"(d[1]), "+f"(d[2]), "+f"(d[3])
        : "r"(a[0]), "r"(a[1]), "r"(a[2]), "r"(a[3]), "r"(b0), "r"(b1));
}

__global__ __launch_bounds__(256, 2)
void k_gemm_self(const float* __restrict__ feat,
                 const float* __restrict__ Wself,
                 const float* __restrict__ bself,
                 float* __restrict__ out) {
    __shared__ uint32_t sA_hi[2048], sA_lo[2048];   // 16 slots x 32 lanes x 4
    __shared__ uint32_t sB_hi[2048], sB_lo[2048];

    const int t    = threadIdx.x;
    const int m0   = blockIdx.x * BM;
    const int wid  = t >> 5;
    const int lane = t & 31;
    const int wm   = wid & 3;        // m offset wm*32
    const int wn   = wid >> 2;       // n offset wn*64
    const int grp  = lane >> 2;
    const int tig  = lane & 3;

    float acc[2][8][4];
    #pragma unroll
    for (int mi = 0; mi < 2; mi++)
        #pragma unroll
        for (int ni = 0; ni < 8; ni++)
            #pragma unroll
            for (int r = 0; r < 4; r++) acc[mi][ni][r] = 0.f;

    for (int kc = 0; kc < IN_F; kc += BK) {
        // --- Stage A tile into fragment-packed layout ---
        #pragma unroll
        for (int l = 0; l < 2; l++) {
            int f4  = t + l * 256;
            int row = f4 >> 2;        // m_local 0..127
            int kq  = f4 & 3;         // k quarter: k_local = kq*4 + jj
            int gr  = m0 + row;
            float4 v = make_float4(0.f, 0.f, 0.f, 0.f);
            if (gr < NN)
                v = *reinterpret_cast<const float4*>(
                        feat + (size_t)gr * IN_F + kc + kq * 4);
            int a_wm  = row >> 5;
            int a_mi  = (row >> 4) & 1;
            int a_grp = row & 7;
            int a_b   = (row >> 3) & 1;
            int slotA = (a_wm * 2 + a_mi) * 2 + (kq >> 1);
            int reg   = (kq & 1) * 2 + a_b;
            int base  = slotA * 128 + a_grp * 16 + reg;   // + jj*4
            uint32_t h, lo;
            split_tf32(v.x, h, lo); sA_hi[base     ] = h; sA_lo[base     ] = lo;
            split_tf32(v.y, h, lo); sA_hi[base +  4] = h; sA_lo[base +  4] = lo;
            split_tf32(v.z, h, lo); sA_hi[base +  8] = h; sA_lo[base +  8] = lo;
            split_tf32(v.w, h, lo); sA_hi[base + 12] = h; sA_lo[base + 12] = lo;
        }
        // --- Stage B tile into fragment-packed layout ---
        #pragma unroll
        for (int l = 0; l < 2; l++) {
            int f4 = t + l * 256;
            int kr = f4 >> 5;         // k_local 0..15
            int nq = f4 & 31;         // c = nq*4 + jj
            float4 v = *reinterpret_cast<const float4*>(
                           Wself + (size_t)(kc + kr) * 128 + nq * 4);
            int b_tig = kr & 3;
            int b_kh  = (kr >> 2) & 1;
            int b_ks8 = kr >> 3;
            float vv[4] = {v.x, v.y, v.z, v.w};
            #pragma unroll
            for (int jj = 0; jj < 4; jj++) {
                int c    = nq * 4 + jj;
                int b_wn = c >> 6;
                int b_ni = (c >> 3) & 7;
                int b_grp= c & 7;
                int slotB = (b_wn * 4 + (b_ni >> 1)) * 2 + b_ks8;
                int word  = slotB * 128 + (b_grp * 4 + b_tig) * 4
                          + (b_ni & 1) * 2 + b_kh;
                uint32_t h, lo;
                split_tf32(vv[jj], h, lo);
                sB_hi[word] = h; sB_lo[word] = lo;
            }
        }
        __syncthreads();

        #pragma unroll
        for (int ks8 = 0; ks8 < 2; ks8++) {
            // A fragments: one LDS.128 per (mi, hi/lo)
            uint4 ah[2], al[2];
            #pragma unroll
            for (int mi = 0; mi < 2; mi++) {
                int slotA = (wm * 2 + mi) * 2 + ks8;
                ah[mi] = *reinterpret_cast<const uint4*>(&sA_hi[slotA * 128 + lane * 4]);
                al[mi] = *reinterpret_cast<const uint4*>(&sA_lo[slotA * 128 + lane * 4]);
            }
            #pragma unroll
            for (int nip = 0; nip < 4; nip++) {
                int slotB = (wn * 4 + nip) * 2 + ks8;
                uint4 bh = *reinterpret_cast<const uint4*>(&sB_hi[slotB * 128 + lane * 4]);
                uint4 bl = *reinterpret_cast<const uint4*>(&sB_lo[slotB * 128 + lane * 4]);
                #pragma unroll
                for (int mi = 0; mi < 2; mi++) {
                    const uint32_t* ahp = reinterpret_cast<const uint32_t*>(&ah[mi]);
                    const uint32_t* alp = reinterpret_cast<const uint32_t*>(&al[mi]);
                    // ni = 2*nip  (regs .x,.y)
                    mma_tf32(acc[mi][2 * nip    ], ahp, bh.x, bh.y);  // hi*hi
                    mma_tf32(acc[mi][2 * nip    ], ahp, bl.x, bl.y);  // hi*lo
                    mma_tf32(acc[mi][2 * nip    ], alp, bh.x, bh.y);  // lo*hi
                    // ni = 2*nip+1 (regs .z,.w)
                    mma_tf32(acc[mi][2 * nip + 1], ahp, bh.z, bh.w);
                    mma_tf32(acc[mi][2 * nip + 1], ahp, bl.z, bl.w);
                    mma_tf32(acc[mi][2 * nip + 1], alp, bh.z, bh.w);
                }
            }
        }
        __syncthreads();
    }

    // Epilogue: acc c0,c1 -> (row grp, cols 2tig,2tig+1); c2,c3 -> row grp+8
    #pragma unroll
    for (int mi = 0; mi < 2; mi++) {
        int rbase = m0 + wm * 32 + mi * 16 + grp;
        #pragma unroll
        for (int ni = 0; ni < 8; ni++) {
            int c = wn * 64 + ni * 8 + tig * 2;
            float bx = bself[c], by = bself[c + 1];
            if (rbase < NN) {
                float2 v0 = make_float2(acc[mi][ni][0] + bx, acc[mi][ni][1] + by);
                *reinterpret_cast<float2*>(out + (size_t)rbase * IN_F + c) = v0;
            }
            if (rbase + 8 < NN) {
                float2 v1 = make_float2(acc[mi][ni][2] + bx, acc[mi][ni][3] + by);
                *reinterpret_cast<float2*>(out + (size_t)(rbase + 8) * IN_F + c) = v1;
            }
        }
    }
}

// ---------------------------------------------------------------------------
// Launch: anti-interference schedule (CSR branch concurrent; the two
// l1tex-heavy kernels serialized). gemm_self at profiled slot 4.
// ---------------------------------------------------------------------------
extern "C" void kernel_launch(void* const* d_in, const int* in_sizes, int n_in,
                              void* d_out, int out_size) {
    const float* feat   = (const float*)d_in[0];
    const float* tkv    = (const float*)d_in[1];
    const int*   tki    = (const int*)  d_in[2];
    const int*   src    = (const int*)  d_in[3];
    const int*   dst    = (const int*)  d_in[4];
    const float* Wself  = (const float*)d_in[5];
    const float* bself  = (const float*)d_in[6];
    const float* Wneigh = (const float*)d_in[7];
    float* out = (float*)d_out;

    static cudaStream_t s1 = nullptr;
    static cudaEvent_t evRoot = nullptr, evCsr = nullptr;
    if (s1 == nullptr) {
        cudaStreamCreateWithFlags(&s1, cudaStreamNonBlocking);
        cudaEventCreateWithFlags(&evRoot, cudaEventDisableTiming);
        cudaEventCreateWithFlags(&evCsr,  cudaEventDisableTiming);
    }

    // Fork CSR branch
    cudaEventRecord(evRoot, 0);
    cudaStreamWaitEvent(s1, evRoot, 0);

    k_zero_deg<<<(NN + 255) / 256, 256, 0, s1>>>();                 // 1
    k_deg<<<(EE / 4 + 255) / 256, 256, 0, s1>>>(dst);               // 2
    k_scan<<<1, SCAN_T, 0, s1>>>();                                 // 3

    // Main stream: gemm_self (slot 4, profiled) then sparse_gemm — serialized
    k_gemm_self<<<(NN + BM - 1) / BM, 256>>>(feat, Wself, bself, out);   // 4

    k_fill<<<(EE / 2 + 255) / 256, 256, 0, s1>>>(src, dst);         // 5
    cudaEventRecord(evCsr, s1);

    k_sparse_gemm<<<(NN + SG_WARPS - 1) / SG_WARPS, 256>>>(tkv, tki, Wneigh); // 6

    // Join CSR, then gather+add
    cudaStreamWaitEvent(0, evCsr, 0);
    k_gather_add<<<(NN + 7) / 8, 256>>>(out);                       // 7
}